// round 14
// baseline (speedup 1.0000x reference)
#include <cuda_runtime.h>
#include <cuda_fp16.h>
#include <stdint.h>

#define Bsz 512
#define Tsz 1024
#define Csz 64
#define Hsz 128

static const int BTILE   = 64;
static const int NTHR    = 512;   // 16 warps
static const int HSTRIDE = 136;   // halves per batch row (128 + 8 pad) -> 272B, conflict-free

// dynamic smem (bytes):
//   [0,131072)        W fp16 A-fragment-ready (pre-scaled: i,f,o rows *0.5)
//   [131072,+17408)   h buf0 fp16 (64 x 136)
//   [148480,+17408)   h buf1 fp16
//   [165888,+512)     x_sm fp32 (2 x 64)
//   [166400,+32768)   hf_sm fp32 (64 x 128) final h for fc
static const int SMEM_H0 = 131072;
static const int SMEM_H1 = SMEM_H0 + 17408;
static const int SMEM_X  = SMEM_H1 + 17408;
static const int SMEM_HF = SMEM_X + 512;
static const int SMEM_TOTAL = SMEM_HF + 32768;   // 199168 B

__device__ __forceinline__ unsigned pack2(float a, float b) {
    __half2 h = __floats2half2_rn(a, b);
    return *reinterpret_cast<unsigned*>(&h);
}

__device__ __forceinline__ void mma16816(float* c, uint4 a, unsigned b0, unsigned b1) {
    asm volatile(
        "mma.sync.aligned.m16n8k16.row.col.f32.f16.f16.f32 "
        "{%0,%1,%2,%3}, {%4,%5,%6,%7}, {%8,%9}, {%0,%1,%2,%3};\n"
        : "+f"(c[0]), "+f"(c[1]), "+f"(c[2]), "+f"(c[3])
        : "r"(a.x), "r"(a.y), "r"(a.z), "r"(a.w), "r"(b0), "r"(b1));
}

__device__ __forceinline__ void ldsm_x4(unsigned& r0, unsigned& r1,
                                        unsigned& r2, unsigned& r3, uint32_t addr) {
    asm volatile("ldmatrix.sync.aligned.m8n8.x4.shared.b16 {%0,%1,%2,%3}, [%4];"
        : "=r"(r0), "=r"(r1), "=r"(r2), "=r"(r3) : "r"(addr));
}

__device__ __forceinline__ __half2 tanh2(__half2 x) {
    __half2 y;
    asm("tanh.approx.f16x2 %0, %1;"
        : "=r"(*reinterpret_cast<unsigned*>(&y))
        : "r"(*reinterpret_cast<unsigned*>(&x)));
    return y;
}

extern __shared__ unsigned char smem_raw[];

__global__ void __launch_bounds__(NTHR, 1)
lstm_fused_kernel(const float* __restrict__ x,     // [B,T,C]
                  const float* __restrict__ W_ih,  // [C,4H]
                  const float* __restrict__ W_hh,  // [C,4H,H]
                  const float* __restrict__ b_ih,  // [C,4H]
                  const float* __restrict__ b_hh,  // [C,4H]
                  const float* __restrict__ W_fc,  // [C,H]
                  const float* __restrict__ b_fc,  // [C]
                  float* __restrict__ out)         // [B,C]
{
    const int btile = blockIdx.x;   // 0..7
    const int ch    = blockIdx.y;   // 0..63
    const int tid   = threadIdx.x;
    const int w     = tid >> 5;
    const int l     = tid & 31;
    const int gid   = l >> 2;       // 0..7
    const int q     = l & 3;        // 0..3

    __half* Wfr   = (__half*)(smem_raw);
    __half* h_sm0 = (__half*)(smem_raw + SMEM_H0);
    __half* h_sm1 = (__half*)(smem_raw + SMEM_H1);
    float*  x_sm  = (float*)(smem_raw + SMEM_X);
    float*  hf_sm = (float*)(smem_raw + SMEM_HF);

    const int j = 8 * w + gid;   // hidden unit owned by this lane group

    // ---- Stage W_hh[ch] fp16 A-fragment-ready, gate-interleaved rows,
    //      sigmoid-gate rows (i,f,o) pre-scaled by 0.5 for tanh-identity sigmoid ----
    {
        const float* Wc = W_hh + (size_t)ch * (4 * Hsz * Hsz);
        #pragma unroll
        for (int mt = 0; mt < 2; ++mt) {
            #pragma unroll
            for (int ks = 0; ks < 8; ++ks) {
                unsigned u[4];
                #pragma unroll
                for (int p = 0; p < 4; ++p) {
                    // p0:(gid,2q) p1:(gid+8,2q) p2:(gid,2q+8) p3:(gid+8,2q+8)
                    int r16 = (p & 1) ? (gid + 8) : gid;
                    int kk  = ks * 16 + q * 2 + ((p & 2) ? 8 : 0);
                    int G   = mt * 2 + (r16 >= 8 ? 1 : 0);  // 0:i 1:f 2:g 3:o
                    int row = G * 128 + 8 * w + (r16 & 7);
                    float sc = (G == 2) ? 1.0f : 0.5f;
                    float2 v = *(const float2*)(Wc + row * Hsz + kk);
                    u[p] = pack2(v.x * sc, v.y * sc);
                }
                uint4 frag; frag.x = u[0]; frag.y = u[1]; frag.z = u[2]; frag.w = u[3];
                int fidx = ((w * 2 + mt) * 8 + ks) * 32 + l;
                *(uint4*)(Wfr + fidx * 8) = frag;
            }
        }
    }

    // per-lane input weight + combined bias, splatted to half2 (i,f,o pre-scaled 0.5)
    __half2 wih2[4], bia2[4];
    #pragma unroll
    for (int G = 0; G < 4; ++G) {
        int row = G * 128 + j;
        float sc = (G == 2) ? 1.0f : 0.5f;
        float wv = W_ih[ch * 512 + row] * sc;
        float bv = (b_ih[ch * 512 + row] + b_hh[ch * 512 + row]) * sc;
        wih2[G] = __floats2half2_rn(wv, wv);
        bia2[G] = __floats2half2_rn(bv, bv);
    }
    const __half2 h05 = __floats2half2_rn(0.5f, 0.5f);

    // ldmatrix lane addresses: 4 x (x4 load) per ks, covering n-tiles (2v, 2v+1)
    const int mi = l >> 3;         // matrix index 0..3
    const int rr = l & 7;
    uint32_t loff[4];
    #pragma unroll
    for (int v = 0; v < 4; ++v) {
        int b = 16 * v + ((mi >> 1) << 3) + rr;
        loff[v] = (uint32_t)((b * HSTRIDE + (mi & 1) * 8) * 2);   // bytes
    }
    const uint32_t h0a = (uint32_t)__cvta_generic_to_shared(h_sm0);
    const uint32_t h1a = (uint32_t)__cvta_generic_to_shared(h_sm1);

    // zero h buf0
    for (int i = tid; i < BTILE * HSTRIDE; i += NTHR) h_sm0[i] = __float2half(0.0f);

    __half2 cst2[8];
    #pragma unroll
    for (int i = 0; i < 8; ++i) cst2[i] = __floats2half2_rn(0.0f, 0.0f);

    const float* xb = x + ((size_t)(btile * 64) * Tsz) * Csz + ch;

    // preload x_0 into x_sm[0]
    if (tid < 64) x_sm[tid] = __ldg(xb + ((size_t)tid * Tsz) * Csz);
    __syncthreads();

    #pragma unroll 1
    for (int t = 0; t < Tsz; ++t) {
        // prefetch x_{t+1}
        float xv = 0.0f;
        if (tid < 64 && t + 1 < Tsz)
            xv = __ldg(xb + ((size_t)tid * Tsz + (t + 1)) * Csz);

        const uint32_t hb = (t & 1) ? h1a : h0a;

        float acc[2][8][4];
        #pragma unroll
        for (int mt = 0; mt < 2; ++mt)
            #pragma unroll
            for (int n = 0; n < 8; ++n)
                #pragma unroll
                for (int r = 0; r < 4; ++r) acc[mt][n][r] = 0.0f;

        // gates[512x64] = W_hh * h_t  (read h buf t&1)
        #pragma unroll
        for (int ks = 0; ks < 8; ++ks) {
            uint4 A0 = *(const uint4*)(Wfr + (((w * 2 + 0) * 8 + ks) * 32 + l) * 8);
            uint4 A1 = *(const uint4*)(Wfr + (((w * 2 + 1) * 8 + ks) * 32 + l) * 8);
            #pragma unroll
            for (int v = 0; v < 4; ++v) {
                unsigned b0a, b1a, b0b, b1b;
                ldsm_x4(b0a, b1a, b0b, b1b, hb + loff[v] + ks * 32);
                mma16816(acc[0][2 * v    ], A0, b0a, b1a);
                mma16816(acc[1][2 * v    ], A1, b0a, b1a);
                mma16816(acc[0][2 * v + 1], A0, b0b, b1b);
                mma16816(acc[1][2 * v + 1], A1, b0b, b1b);
            }
        }

        if (tid < 64) x_sm[((t + 1) & 1) * 64 + tid] = xv;

        __half* h_next = (t & 1) ? h_sm0 : h_sm1;   // write buf (t+1)&1
        const float* x_cur = x_sm + (t & 1) * 64;
        const bool last = (t == Tsz - 1);

        // elementwise, fully f16x2: pair = adjacent batches (s=0,1)
        #pragma unroll
        for (int n = 0; n < 8; ++n) {
            int b0 = n * 8 + q * 2;
            float2 xx = *(const float2*)(x_cur + b0);
            __half2 xx2 = __floats2half2_rn(xx.x, xx.y);
            __half2 pi = __hfma2(xx2, wih2[0],
                          __hadd2(__floats2half2_rn(acc[0][n][0], acc[0][n][1]), bia2[0]));
            __half2 pf = __hfma2(xx2, wih2[1],
                          __hadd2(__floats2half2_rn(acc[0][n][2], acc[0][n][3]), bia2[1]));
            __half2 pg = __hfma2(xx2, wih2[2],
                          __hadd2(__floats2half2_rn(acc[1][n][0], acc[1][n][1]), bia2[2]));
            __half2 po = __hfma2(xx2, wih2[3],
                          __hadd2(__floats2half2_rn(acc[1][n][2], acc[1][n][3]), bia2[3]));
            __half2 ig = __hfma2(tanh2(pi), h05, h05);
            __half2 fg = __hfma2(tanh2(pf), h05, h05);
            __half2 gg = tanh2(pg);
            __half2 og = __hfma2(tanh2(po), h05, h05);
            __half2 cc = __hfma2(fg, cst2[n], __hmul2(ig, gg));
            cst2[n] = cc;
            __half2 hh = __hmul2(og, tanh2(cc));
            h_next[b0 * HSTRIDE + j]       = __low2half(hh);
            h_next[(b0 + 1) * HSTRIDE + j] = __high2half(hh);
            if (last) {
                hf_sm[b0 * 128 + j]       = __low2float(hh);
                hf_sm[(b0 + 1) * 128 + j] = __high2float(hh);
            }
        }
        __syncthreads();   // publish h_{t+1}, x_{t+1}
    }

    // per-channel Linear(H,1) on fp32 h_T
    if (tid < 64) {
        int b = tid;
        float s = b_fc[ch];
        const float* wf = W_fc + ch * 128;
        #pragma unroll 8
        for (int jj = 0; jj < 128; ++jj)
            s += wf[jj] * hf_sm[b * 128 + jj];
        out[((size_t)(btile * 64 + b)) * Csz + ch] = s;
    }
}

extern "C" void kernel_launch(void* const* d_in, const int* in_sizes, int n_in,
                              void* d_out, int out_size)
{
    const float* x    = (const float*)d_in[0];
    const float* W_ih = (const float*)d_in[1];
    const float* W_hh = (const float*)d_in[2];
    const float* b_ih = (const float*)d_in[3];
    const float* b_hh = (const float*)d_in[4];
    const float* W_fc = (const float*)d_in[5];
    const float* b_fc = (const float*)d_in[6];
    float* out = (float*)d_out;

    cudaFuncSetAttribute(lstm_fused_kernel,
                         cudaFuncAttributeMaxDynamicSharedMemorySize, SMEM_TOTAL);

    dim3 grid(Bsz / BTILE, Csz);   // (8, 64) = 512 CTAs
    lstm_fused_kernel<<<grid, NTHR, SMEM_TOTAL>>>(x, W_ih, W_hh, b_ih, b_hh,
                                                  W_fc, b_fc, out);
}

// round 17
// speedup vs baseline: 1.0412x; 1.0412x over previous
#include <cuda_runtime.h>
#include <cuda_fp16.h>
#include <stdint.h>

#define Bsz 512
#define Tsz 1024
#define Csz 64
#define Hsz 128

static const int BTILE   = 64;
static const int NTHR    = 512;   // 16 warps = 2 independent groups of 8
static const int HSTRIDE = 136;   // halves per batch row (128 + 8 pad) -> 272B, conflict-free

// dynamic smem (bytes):
//   [0,131072)        W fp16 A-fragment-ready (pre-scaled: i,f,o rows *0.5)
//   [131072,+17408)   h buf0 fp16 (64 x 136)
//   [148480,+17408)   h buf1 fp16
//   [165888,+512)     x_sm fp32 (2 x 64)
//   [166400,+32768)   hf_sm fp32 (64 x 128) final h for fc
static const int SMEM_H0 = 131072;
static const int SMEM_H1 = SMEM_H0 + 17408;
static const int SMEM_X  = SMEM_H1 + 17408;
static const int SMEM_HF = SMEM_X + 512;
static const int SMEM_TOTAL = SMEM_HF + 32768;   // 199168 B

__device__ __forceinline__ unsigned pack2(float a, float b) {
    __half2 h = __floats2half2_rn(a, b);
    return *reinterpret_cast<unsigned*>(&h);
}

__device__ __forceinline__ void mma16816(float* c, uint4 a, unsigned b0, unsigned b1) {
    asm volatile(
        "mma.sync.aligned.m16n8k16.row.col.f32.f16.f16.f32 "
        "{%0,%1,%2,%3}, {%4,%5,%6,%7}, {%8,%9}, {%0,%1,%2,%3};\n"
        : "+f"(c[0]), "+f"(c[1]), "+f"(c[2]), "+f"(c[3])
        : "r"(a.x), "r"(a.y), "r"(a.z), "r"(a.w), "r"(b0), "r"(b1));
}

__device__ __forceinline__ void ldsm_x4(unsigned& r0, unsigned& r1,
                                        unsigned& r2, unsigned& r3, uint32_t addr) {
    asm volatile("ldmatrix.sync.aligned.m8n8.x4.shared.b16 {%0,%1,%2,%3}, [%4];"
        : "=r"(r0), "=r"(r1), "=r"(r2), "=r"(r3) : "r"(addr));
}

__device__ __forceinline__ float tanh_apx(float x) {
    float y; asm("tanh.approx.f32 %0, %1;" : "=f"(y) : "f"(x)); return y;
}

__device__ __forceinline__ void barg(int id) {
    asm volatile("bar.sync %0, 256;" :: "r"(id) : "memory");
}

extern __shared__ unsigned char smem_raw[];

__global__ void __launch_bounds__(NTHR, 1)
lstm_fused_kernel(const float* __restrict__ x,     // [B,T,C]
                  const float* __restrict__ W_ih,  // [C,4H]
                  const float* __restrict__ W_hh,  // [C,4H,H]
                  const float* __restrict__ b_ih,  // [C,4H]
                  const float* __restrict__ b_hh,  // [C,4H]
                  const float* __restrict__ W_fc,  // [C,H]
                  const float* __restrict__ b_fc,  // [C]
                  float* __restrict__ out)         // [B,C]
{
    const int btile = blockIdx.x;   // 0..7
    const int ch    = blockIdx.y;   // 0..63
    const int tid   = threadIdx.x;
    const int w     = tid >> 5;     // 0..15
    const int l     = tid & 31;
    const int g     = w >> 3;       // group 0/1 -> batches [32g, 32g+32)
    const int wg8   = w & 7;        // warp-in-group
    const int gid   = l >> 2;       // 0..7
    const int q     = l & 3;        // 0..3

    __half* Wfr   = (__half*)(smem_raw);
    __half* h_sm0 = (__half*)(smem_raw + SMEM_H0);
    __half* h_sm1 = (__half*)(smem_raw + SMEM_H1);
    float*  x_sm  = (float*)(smem_raw + SMEM_X);
    float*  hf_sm = (float*)(smem_raw + SMEM_HF);

    // ---- Stage W_hh[ch] fp16 A-fragment-ready (all 16 warps; warp w stages
    //      j-block 8w). Gate-interleaved rows; i,f,o rows pre-scaled by 0.5 ----
    {
        const float* Wc = W_hh + (size_t)ch * (4 * Hsz * Hsz);
        #pragma unroll
        for (int mt = 0; mt < 2; ++mt) {
            #pragma unroll
            for (int ks = 0; ks < 8; ++ks) {
                unsigned u[4];
                #pragma unroll
                for (int p = 0; p < 4; ++p) {
                    int r16 = (p & 1) ? (gid + 8) : gid;
                    int kk  = ks * 16 + q * 2 + ((p & 2) ? 8 : 0);
                    int G   = mt * 2 + (r16 >= 8 ? 1 : 0);  // 0:i 1:f 2:g 3:o
                    int row = G * 128 + 8 * w + (r16 & 7);
                    float sc = (G == 2) ? 1.0f : 0.5f;
                    float2 v = *(const float2*)(Wc + row * Hsz + kk);
                    u[p] = pack2(v.x * sc, v.y * sc);
                }
                uint4 frag; frag.x = u[0]; frag.y = u[1]; frag.z = u[2]; frag.w = u[3];
                int fidx = ((w * 2 + mt) * 8 + ks) * 32 + l;
                *(uint4*)(Wfr + fidx * 8) = frag;
            }
        }
    }

    // This warp consumes j-blocks 2*wg8 and 2*wg8+1 (16 hidden units)
    // per-lane input weight + combined bias (i,f,o pre-scaled by 0.5)
    float wih[2][4], bia[2][4];
    #pragma unroll
    for (int jj = 0; jj < 2; ++jj) {
        int j = 16 * wg8 + 8 * jj + gid;
        #pragma unroll
        for (int G = 0; G < 4; ++G) {
            int row = G * 128 + j;
            float sc = (G == 2) ? 1.0f : 0.5f;
            wih[jj][G] = W_ih[ch * 512 + row] * sc;
            bia[jj][G] = (b_ih[ch * 512 + row] + b_hh[ch * 512 + row]) * sc;
        }
    }

    // ldmatrix lane addresses: 2 x (x4) per ks covering this group's 32 batches
    const int mi = l >> 3;
    const int rr = l & 7;
    uint32_t loff[2];
    #pragma unroll
    for (int v = 0; v < 2; ++v) {
        int b = 32 * g + 16 * v + ((mi >> 1) << 3) + rr;
        loff[v] = (uint32_t)((b * HSTRIDE + (mi & 1) * 8) * 2);   // bytes
    }
    const uint32_t h0a = (uint32_t)__cvta_generic_to_shared(h_sm0);
    const uint32_t h1a = (uint32_t)__cvta_generic_to_shared(h_sm1);

    // zero h buf0
    for (int i = tid; i < BTILE * HSTRIDE; i += NTHR) h_sm0[i] = __float2half(0.0f);

    float cst[16];
    #pragma unroll
    for (int i = 0; i < 16; ++i) cst[i] = 0.0f;

    const float* xb = x + ((size_t)(btile * 64) * Tsz) * Csz + ch;

    // preload x_0
    if (tid < 64) x_sm[tid] = __ldg(xb + ((size_t)tid * Tsz) * Csz);
    __syncthreads();   // W, h0, x0 visible to all

    const bool xldr = (wg8 == 0);        // warp 8g loads its group's x
    const int  xbat = 32 * g + l;        // batch this lane loads

    #pragma unroll 1
    for (int t = 0; t < Tsz; ++t) {
        float xv = 0.0f;
        if (xldr && t + 1 < Tsz)
            xv = __ldg(xb + ((size_t)xbat * Tsz + (t + 1)) * Csz);

        const uint32_t hb = (t & 1) ? h1a : h0a;

        float acc[4][4][4];   // [m-tile p][n-tile][frag]
        #pragma unroll
        for (int p = 0; p < 4; ++p)
            #pragma unroll
            for (int n = 0; n < 4; ++n)
                #pragma unroll
                for (int r = 0; r < 4; ++r) acc[p][n][r] = 0.0f;

        // gates[512 x 32(this group)] = W_hh * h_t
        #pragma unroll
        for (int ks = 0; ks < 8; ++ks) {
            uint4 A[4];
            #pragma unroll
            for (int p = 0; p < 4; ++p) {
                int slot = (2 * wg8 + (p >> 1)) * 2 + (p & 1);   // (j-block, mt)
                A[p] = *(const uint4*)(Wfr + ((slot * 8 + ks) * 32 + l) * 8);
            }
            #pragma unroll
            for (int v = 0; v < 2; ++v) {
                unsigned b0a, b1a, b0b, b1b;
                ldsm_x4(b0a, b1a, b0b, b1b, hb + loff[v] + ks * 32);
                #pragma unroll
                for (int p = 0; p < 4; ++p) {
                    mma16816(acc[p][2 * v    ], A[p], b0a, b1a);
                    mma16816(acc[p][2 * v + 1], A[p], b0b, b1b);
                }
            }
        }

        if (xldr) x_sm[((t + 1) & 1) * 64 + xbat] = xv;

        __half* h_next = (t & 1) ? h_sm0 : h_sm1;
        const float* x_cur = x_sm + (t & 1) * 64;
        const bool last = (t == Tsz - 1);

        #pragma unroll
        for (int n = 0; n < 4; ++n) {
            #pragma unroll
            for (int s = 0; s < 2; ++s) {
                int b = 32 * g + n * 8 + q * 2 + s;
                float xx = x_cur[b];
                #pragma unroll
                for (int jj = 0; jj < 2; ++jj) {
                    int j = 16 * wg8 + 8 * jj + gid;
                    float pi = acc[2 * jj + 0][n][0 + s] + xx * wih[jj][0] + bia[jj][0];
                    float pf = acc[2 * jj + 0][n][2 + s] + xx * wih[jj][1] + bia[jj][1];
                    float pg = acc[2 * jj + 1][n][0 + s] + xx * wih[jj][2] + bia[jj][2];
                    float po = acc[2 * jj + 1][n][2 + s] + xx * wih[jj][3] + bia[jj][3];
                    float ig = 0.5f * tanh_apx(pi) + 0.5f;
                    float fg = 0.5f * tanh_apx(pf) + 0.5f;
                    float gg = tanh_apx(pg);
                    float og = 0.5f * tanh_apx(po) + 0.5f;
                    int ci = jj * 8 + n * 2 + s;
                    float cc = fg * cst[ci] + ig * gg;
                    cst[ci] = cc;
                    float hh = og * tanh_apx(cc);
                    h_next[b * HSTRIDE + j] = __float2half(hh);
                    if (last) hf_sm[b * 128 + j] = hh;
                }
            }
        }
        barg(1 + g);   // group-local: publish this group's h_{t+1}, x_{t+1}
    }

    __syncthreads();   // both groups done

    // per-channel Linear(H,1) on fp32 h_T
    if (tid < 64) {
        int b = tid;
        float s = b_fc[ch];
        const float* wf = W_fc + ch * 128;
        #pragma unroll 8
        for (int jj = 0; jj < 128; ++jj)
            s += wf[jj] * hf_sm[b * 128 + jj];
        out[((size_t)(btile * 64 + b)) * Csz + ch] = s;
    }
}

extern "C" void kernel_launch(void* const* d_in, const int* in_sizes, int n_in,
                              void* d_out, int out_size)
{
    const float* x    = (const float*)d_in[0];
    const float* W_ih = (const float*)d_in[1];
    const float* W_hh = (const float*)d_in[2];
    const float* b_ih = (const float*)d_in[3];
    const float* b_hh = (const float*)d_in[4];
    const float* W_fc = (const float*)d_in[5];
    const float* b_fc = (const float*)d_in[6];
    float* out = (float*)d_out;

    cudaFuncSetAttribute(lstm_fused_kernel,
                         cudaFuncAttributeMaxDynamicSharedMemorySize, SMEM_TOTAL);

    dim3 grid(Bsz / BTILE, Csz);   // (8, 64) = 512 CTAs
    lstm_fused_kernel<<<grid, NTHR, SMEM_TOTAL>>>(x, W_ih, W_hh, b_ih, b_hh,
                                                  W_fc, b_fc, out);
}